// round 10
// baseline (speedup 1.0000x reference)
#include <cuda_runtime.h>
#include <math.h>

#define Bsz 4
#define Dd  96
#define Hh  64
#define Ww  64
#define Ll  4096
#define Kk  4
#define Nn  16
#define Rr  6
#define C38 38
#define NCk 64   // number of chunks
#define LCk 64   // chunk length (NCk*LCk == Ll)

// ---------------- scratch (__device__ globals; no allocations) ----------------
__device__ float  g_xpf  [Bsz*Ll*Dd];           // x permuted (B,L,D), row-major spatial
__device__ float  g_xpt  [Bsz*Ll*Dd];           // x permuted (B,L,D), col-major spatial
__device__ float  g_delta[Bsz*Kk*Ll*Dd];        // softplus(delta) (B,K,L,D)
__device__ float  g_Bsc  [Bsz*Kk*Ll*Nn];        // Bs (B,K,L,N)
__device__ float  g_Csc  [Bsz*Kk*Ll*Nn];        // Cs (B,K,L,N)
__device__ float2 g_Phc  [Bsz*Kk*NCk*Dd*Nn];    // interleaved (chunk decay P, end state hc)
__device__ float  g_hin  [Bsz*Kk*NCk*Dd*Nn];    // chunk incoming states
__device__ float  g_ys   [Kk*Bsz*Ll*Dd];        // per-direction y in merge-target space

__device__ __forceinline__ float ex2f(float x){
    float r; asm("ex2.approx.ftz.f32 %0, %1;" : "=f"(r) : "f"(x)); return r;
}
__device__ __forceinline__ float lg2f(float x){
    float r; asm("lg2.approx.ftz.f32 %0, %1;" : "=f"(r) : "f"(x)); return r;
}
__device__ __forceinline__ float softplus_f(float x){
    // max(x,0) + ln2*log2(1 + 2^(-|x|*log2e))
    float e = ex2f(-fabsf(x)*1.4426950408889634f);
    return fmaxf(x, 0.f) + 0.6931471805599453f*lg2f(1.f + e);
}

// ---------------- kernel 1: transpose x -> (B,L,D) in both traversal orders ---
__global__ void k_transpose(const float* __restrict__ x){
    __shared__ float tile[32][33];
    int b = blockIdx.z, d0 = blockIdx.y*32, l0 = blockIdx.x*32;
    int tx = threadIdx.x, ty = threadIdx.y;     // block (32,8)
    #pragma unroll
    for (int i=0;i<4;i++){
        tile[ty+8*i][tx] = x[((long)b*Dd + d0+ty+8*i)*Ll + l0+tx];
    }
    __syncthreads();
    #pragma unroll
    for (int i=0;i<4;i++){
        int l = l0 + ty + 8*i;
        int d = d0 + tx;
        float v = tile[tx][ty+8*i];
        g_xpf[((long)b*Ll + l)*Dd + d] = v;
        int lp = ((l & 63) << 6) | (l >> 6);    // spatial transpose index
        g_xpt[((long)b*Ll + lp)*Dd + d] = v;
    }
}

// ---------------- kernel 2: projections (x_dbl split + dt proj + softplus) ----
__global__ void __launch_bounds__(128) k_proj(const float* __restrict__ xw,
                                              const float* __restrict__ dtw,
                                              const float* __restrict__ dtb){
    __shared__ float swx [2*C38*Dd];
    __shared__ float swdt[2*Dd*Rr];
    __shared__ float sbia[2*Dd];
    int o = blockIdx.y, b = blockIdx.z;
    int tid = threadIdx.x;
    for (int i=tid;i<2*C38*Dd;i+=128){
        int ki = i/(C38*Dd); int rem = i - ki*(C38*Dd);
        swx[i] = xw[(o + 2*ki)*C38*Dd + rem];
    }
    for (int i=tid;i<2*Dd*Rr;i+=128){
        int ki = i/(Dd*Rr); int rem = i - ki*(Dd*Rr);
        swdt[i] = dtw[(o + 2*ki)*Dd*Rr + rem];
    }
    for (int i=tid;i<2*Dd;i+=128){
        int ki = i/Dd; int rem = i - ki*Dd;
        sbia[i] = dtb[(o + 2*ki)*Dd + rem];
    }
    __syncthreads();

    int p = blockIdx.x*128 + tid;
    const float* xp = (o==0 ? g_xpf : g_xpt) + ((long)b*Ll + p)*Dd;
    float xv[Dd];
    #pragma unroll
    for (int i=0;i<Dd/4;i++){
        float4 v = reinterpret_cast<const float4*>(xp)[i];
        xv[4*i]=v.x; xv[4*i+1]=v.y; xv[4*i+2]=v.z; xv[4*i+3]=v.w;
    }

    for (int ki=0; ki<2; ki++){
        int k = o + 2*ki;
        int l = (ki==0) ? p : (Ll-1-p);
        const float* wk = swx + ki*C38*Dd;
        long bkl = ((long)(b*Kk + k))*Ll + l;

        // dts (first R rows)
        float dts[Rr];
        #pragma unroll
        for (int c=0;c<Rr;c++){
            float acc = 0.f;
            #pragma unroll
            for (int d=0; d<Dd; d++) acc += xv[d]*wk[c*Dd+d];
            dts[c] = acc;
        }
        // Bs rows
        for (int cc=0; cc<Nn/4; cc++){
            const float* w0 = wk + (Rr + 4*cc)*Dd;
            float a0=0,a1=0,a2=0,a3=0;
            #pragma unroll
            for (int d=0; d<Dd; d++){
                float xd = xv[d];
                a0 += xd*w0[d]; a1 += xd*w0[Dd+d];
                a2 += xd*w0[2*Dd+d]; a3 += xd*w0[3*Dd+d];
            }
            reinterpret_cast<float4*>(g_Bsc + bkl*Nn)[cc] = make_float4(a0,a1,a2,a3);
        }
        // Cs rows
        for (int cc=0; cc<Nn/4; cc++){
            const float* w0 = wk + (Rr + Nn + 4*cc)*Dd;
            float a0=0,a1=0,a2=0,a3=0;
            #pragma unroll
            for (int d=0; d<Dd; d++){
                float xd = xv[d];
                a0 += xd*w0[d]; a1 += xd*w0[Dd+d];
                a2 += xd*w0[2*Dd+d]; a3 += xd*w0[3*Dd+d];
            }
            reinterpret_cast<float4*>(g_Csc + bkl*Nn)[cc] = make_float4(a0,a1,a2,a3);
        }
        // delta = softplus(dts @ dtW + bias)
        const float* wd  = swdt + ki*Dd*Rr;
        const float* bia = sbia + ki*Dd;
        float* dout = g_delta + bkl*Dd;
        for (int dd=0; dd<Dd; dd+=4){
            float aa[4];
            #pragma unroll
            for (int q=0;q<4;q++){
                float acc = bia[dd+q];
                #pragma unroll
                for (int r=0;r<Rr;r++) acc += dts[r]*wd[(dd+q)*Rr + r];
                aa[q] = softplus_f(acc);
            }
            reinterpret_cast<float4*>(dout + dd)[0] = make_float4(aa[0],aa[1],aa[2],aa[3]);
        }
    }
}

// ---------------- kernel 3: pass A — split-N: thread=(d, nh), 8 states each ---
__global__ void __launch_bounds__(2*Dd) k_scanA(const float* __restrict__ A_logs){
    __shared__ float4 sB[LCk*Nn/4];
    int c = blockIdx.x, k = blockIdx.y, b = blockIdx.z;
    int tid = threadIdx.x;
    int nh = tid & 1, d = tid >> 1;
    long bk = (long)b*Kk + k;

    const float4* gB4 = reinterpret_cast<const float4*>(g_Bsc + (bk*Ll + (long)c*LCk)*Nn);
    for (int i=tid; i<LCk*Nn/4; i+=2*Dd) sB[i] = gB4[i];
    __syncthreads();

    float A2[8];
    const float* al = A_logs + (k*Dd + d)*Nn + nh*8;
    #pragma unroll
    for (int n=0;n<8;n++) A2[n] = -__expf(al[n]) * 1.4426950408889634f;

    float h[8];
    #pragma unroll
    for (int n=0;n<8;n++) h[n] = 0.f;
    float S = 0.f;

    const float* dptr = g_delta + (bk*Ll + (long)c*LCk)*Dd + d;
    const float* xp = (k & 1) ? g_xpt : g_xpf;
    int l0 = c*LCk;
    const float* uptr; int ustr;
    if (k < 2){ uptr = xp + ((long)b*Ll + l0)*Dd + d;           ustr =  Dd; }
    else      { uptr = xp + ((long)b*Ll + (Ll-1-l0))*Dd + d;    ustr = -Dd; }

    #pragma unroll 2
    for (int j=0;j<LCk;j++){
        float dlt = dptr[j*Dd];
        float u = *uptr; uptr += ustr;
        float du = dlt*u;
        S += dlt;
        const float4* bj = sB + j*(Nn/4) + nh*2;
        float4 b0 = bj[0], b1 = bj[1];
        h[0] = h[0]*ex2f(dlt*A2[0]) + du*b0.x;
        h[1] = h[1]*ex2f(dlt*A2[1]) + du*b0.y;
        h[2] = h[2]*ex2f(dlt*A2[2]) + du*b0.z;
        h[3] = h[3]*ex2f(dlt*A2[3]) + du*b0.w;
        h[4] = h[4]*ex2f(dlt*A2[4]) + du*b1.x;
        h[5] = h[5]*ex2f(dlt*A2[5]) + du*b1.y;
        h[6] = h[6]*ex2f(dlt*A2[6]) + du*b1.z;
        h[7] = h[7]*ex2f(dlt*A2[7]) + du*b1.w;
    }
    long base = ((bk*NCk + c)*Dd + d)*Nn + nh*8;   // in float2 units
    float4* pp = reinterpret_cast<float4*>(g_Phc + base);
    #pragma unroll
    for (int q=0;q<4;q++){
        pp[q] = make_float4(ex2f(A2[2*q]*S),   h[2*q],
                            ex2f(A2[2*q+1]*S), h[2*q+1]);
    }
}

// ---------------- kernel 4: inter-chunk scan (software-pipelined loads) ------
#define MID_G 16
#define MID_NG (NCk/MID_G)
__global__ void __launch_bounds__(256) k_mid(){
    int g = blockIdx.x*blockDim.x + threadIdx.x;   // B*K*D*N threads
    if (g >= Bsz*Kk*Dd*Nn) return;
    const int STR = Dd*Nn;                         // stride between chunks
    long base0 = g + ((long)(g / (Dd*Nn))) * (long)(NCk-1) * STR;

    float2 PH[2][MID_G];

    #pragma unroll
    for (int i=0;i<MID_G;i++)
        PH[0][i] = g_Phc[base0 + (long)i*STR];

    float hin = 0.f;
    #pragma unroll
    for (int grp=0; grp<MID_NG; grp++){
        int cur = grp & 1, nxt = cur ^ 1;
        if (grp+1 < MID_NG){
            #pragma unroll
            for (int i=0;i<MID_G;i++)
                PH[nxt][i] = g_Phc[base0 + (long)((grp+1)*MID_G + i)*STR];
        }
        #pragma unroll
        for (int i=0;i<MID_G;i++){
            long idx = base0 + (long)(grp*MID_G + i)*STR;
            g_hin[idx] = hin;
            hin = hin*PH[cur][i].x + PH[cur][i].y;
        }
    }
}

// ---------------- kernel 5: pass B — split-N replay, shfl-reduced y ----------
__global__ void __launch_bounds__(2*Dd) k_scanB(const float* __restrict__ A_logs,
                                                const float* __restrict__ Ds){
    __shared__ float4 sB[LCk*Nn/4];
    __shared__ float4 sC[LCk*Nn/4];
    int c = blockIdx.x, k = blockIdx.y, b = blockIdx.z;
    int tid = threadIdx.x;
    int nh = tid & 1, d = tid >> 1;
    long bk = (long)b*Kk + k;

    const float4* gB4 = reinterpret_cast<const float4*>(g_Bsc + (bk*Ll + (long)c*LCk)*Nn);
    const float4* gC4 = reinterpret_cast<const float4*>(g_Csc + (bk*Ll + (long)c*LCk)*Nn);
    for (int i=tid; i<LCk*Nn/4; i+=2*Dd){ sB[i] = gB4[i]; sC[i] = gC4[i]; }
    __syncthreads();

    float A2[8];
    const float* al = A_logs + (k*Dd + d)*Nn + nh*8;
    #pragma unroll
    for (int n=0;n<8;n++) A2[n] = -__expf(al[n]) * 1.4426950408889634f;

    float h[8];
    long base = ((bk*NCk + c)*Dd + d)*Nn + nh*8;
    {
        float4 v0 = reinterpret_cast<const float4*>(g_hin + base)[0];
        float4 v1 = reinterpret_cast<const float4*>(g_hin + base)[1];
        h[0]=v0.x; h[1]=v0.y; h[2]=v0.z; h[3]=v0.w;
        h[4]=v1.x; h[5]=v1.y; h[6]=v1.z; h[7]=v1.w;
    }
    float Dskip = (nh==0) ? Ds[k*Dd + d] : 0.f;

    const float* dptr = g_delta + (bk*Ll + (long)c*LCk)*Dd + d;
    const float* xp = (k & 1) ? g_xpt : g_xpf;
    int l0 = c*LCk;
    const float* uptr; int ustr;
    if (k < 2){ uptr = xp + ((long)b*Ll + l0)*Dd + d;        ustr =  Dd; }
    else      { uptr = xp + ((long)b*Ll + (Ll-1-l0))*Dd + d; ustr = -Dd; }

    float* yout = g_ys + ((long)k*Bsz + b)*Ll*Dd + d;

    #pragma unroll 2
    for (int j=0;j<LCk;j++){
        float dlt = dptr[j*Dd];
        float u = *uptr; uptr += ustr;
        float du = dlt*u;
        float yp = Dskip*u;
        const float4* bj = sB + j*(Nn/4) + nh*2;
        const float4* cj = sC + j*(Nn/4) + nh*2;
        float4 b0 = bj[0], b1 = bj[1];
        float4 c0 = cj[0], c1 = cj[1];
        h[0] = h[0]*ex2f(dlt*A2[0]) + du*b0.x;  yp += h[0]*c0.x;
        h[1] = h[1]*ex2f(dlt*A2[1]) + du*b0.y;  yp += h[1]*c0.y;
        h[2] = h[2]*ex2f(dlt*A2[2]) + du*b0.z;  yp += h[2]*c0.z;
        h[3] = h[3]*ex2f(dlt*A2[3]) + du*b0.w;  yp += h[3]*c0.w;
        h[4] = h[4]*ex2f(dlt*A2[4]) + du*b1.x;  yp += h[4]*c1.x;
        h[5] = h[5]*ex2f(dlt*A2[5]) + du*b1.y;  yp += h[5]*c1.y;
        h[6] = h[6]*ex2f(dlt*A2[6]) + du*b1.z;  yp += h[6]*c1.z;
        h[7] = h[7]*ex2f(dlt*A2[7]) + du*b1.w;  yp += h[7]*c1.w;

        float y = yp + __shfl_xor_sync(0xffffffffu, yp, 1);
        if (nh == 0){
            int l = l0 + j;
            int t;
            if (k == 0)      t = l;
            else if (k == 1) t = ((l & 63) << 6) | (l >> 6);
            else if (k == 2) t = Ll-1-l;
            else { int q2 = Ll-1-l; t = ((q2 & 63) << 6) | (q2 >> 6); }
            yout[(long)t*Dd] = y;
        }
    }
}

// ---------------- kernel 6: 4-way merge + LayerNorm --------------------------
__global__ void __launch_bounds__(256) k_merge(const float* __restrict__ lnw,
                                               const float* __restrict__ lnb,
                                               float* __restrict__ out){
    const long BLD = (long)Bsz*Ll*Dd;
    int warp = threadIdx.x >> 5, lane = threadIdx.x & 31;
    int pos = blockIdx.x*8 + warp;
    int b = pos >> 12;              // Ll = 4096
    int l = pos & (Ll-1);
    long base = ((long)b*Ll + l)*Dd;
    float s[3]; float sum = 0.f, sq = 0.f;
    #pragma unroll
    for (int i=0;i<3;i++){
        long off = base + lane + 32*i;
        float v = g_ys[off] + g_ys[off + BLD] + g_ys[off + 2*BLD] + g_ys[off + 3*BLD];
        s[i] = v; sum += v; sq += v*v;
    }
    #pragma unroll
    for (int o2=16;o2>0;o2>>=1){
        sum += __shfl_xor_sync(0xffffffffu, sum, o2);
        sq  += __shfl_xor_sync(0xffffffffu, sq,  o2);
    }
    float mean = sum * (1.f/Dd);
    float var  = sq  * (1.f/Dd) - mean*mean;
    float inv  = rsqrtf(var + 1e-5f);
    #pragma unroll
    for (int i=0;i<3;i++){
        int dch = lane + 32*i;
        out[base + dch] = (s[i]-mean)*inv*lnw[dch] + lnb[dch];
    }
}

// ---------------- launch ------------------------------------------------------
extern "C" void kernel_launch(void* const* d_in, const int* in_sizes, int n_in,
                              void* d_out, int out_size){
    const float* x     = (const float*)d_in[0];
    const float* xw    = (const float*)d_in[1];
    const float* dtw   = (const float*)d_in[2];
    const float* dtb   = (const float*)d_in[3];
    const float* alogs = (const float*)d_in[4];
    const float* Ds    = (const float*)d_in[5];
    const float* lnw   = (const float*)d_in[6];
    const float* lnb   = (const float*)d_in[7];
    float* out = (float*)d_out;

    k_transpose<<<dim3(Ll/32, Dd/32, Bsz), dim3(32,8)>>>(x);
    k_proj     <<<dim3(Ll/128, 2, Bsz), 128>>>(xw, dtw, dtb);
    k_scanA    <<<dim3(NCk, Kk, Bsz), 2*Dd>>>(alogs);
    k_mid      <<<(Bsz*Kk*Dd*Nn + 255)/256, 256>>>();
    k_scanB    <<<dim3(NCk, Kk, Bsz), 2*Dd>>>(alogs, Ds);
    k_merge    <<<Bsz*Ll/8, 256>>>(lnw, lnb, out);
}

// round 11
// speedup vs baseline: 1.1318x; 1.1318x over previous
#include <cuda_runtime.h>
#include <math.h>

#define Bsz 4
#define Dd  96
#define Hh  64
#define Ww  64
#define Ll  4096
#define Kk  4
#define Nn  16
#define Rr  6
#define C38 38
#define NCk 64   // number of chunks
#define LCk 64   // chunk length (NCk*LCk == Ll)

// ---------------- scratch (__device__ globals; no allocations) ----------------
__device__ float  g_xpf  [Bsz*Ll*Dd];           // x permuted (B,L,D), row-major spatial
__device__ float  g_xpt  [Bsz*Ll*Dd];           // x permuted (B,L,D), col-major spatial
__device__ float2 g_ddu  [Bsz*Kk*Ll*Dd];        // (softplus delta, delta*u) (B,K,L,D)
__device__ float  g_Bsc  [Bsz*Kk*Ll*Nn];        // Bs (B,K,L,N)
__device__ float  g_Csc  [Bsz*Kk*Ll*Nn];        // Cs (B,K,L,N)
__device__ float2 g_Phc  [Bsz*Kk*NCk*Dd*Nn];    // interleaved (chunk decay P, end state hc)
__device__ float  g_hin  [Bsz*Kk*NCk*Dd*Nn];    // chunk incoming states
__device__ float  g_ys   [Kk*Bsz*Ll*Dd];        // per-direction y in merge-target space

__device__ __forceinline__ float ex2f(float x){
    float r; asm("ex2.approx.ftz.f32 %0, %1;" : "=f"(r) : "f"(x)); return r;
}
__device__ __forceinline__ float lg2f(float x){
    float r; asm("lg2.approx.ftz.f32 %0, %1;" : "=f"(r) : "f"(x)); return r;
}
__device__ __forceinline__ float softplus_f(float x){
    float e = ex2f(-fabsf(x)*1.4426950408889634f);
    return fmaxf(x, 0.f) + 0.6931471805599453f*lg2f(1.f + e);
}

// ---------------- kernel 1: transpose x -> (B,L,D) in both traversal orders ---
__global__ void k_transpose(const float* __restrict__ x){
    __shared__ float tile[32][33];
    int b = blockIdx.z, d0 = blockIdx.y*32, l0 = blockIdx.x*32;
    int tx = threadIdx.x, ty = threadIdx.y;     // block (32,8)
    #pragma unroll
    for (int i=0;i<4;i++){
        tile[ty+8*i][tx] = x[((long)b*Dd + d0+ty+8*i)*Ll + l0+tx];
    }
    __syncthreads();
    #pragma unroll
    for (int i=0;i<4;i++){
        int l = l0 + ty + 8*i;
        int d = d0 + tx;
        float v = tile[tx][ty+8*i];
        g_xpf[((long)b*Ll + l)*Dd + d] = v;
        int lp = ((l & 63) << 6) | (l >> 6);    // spatial transpose index
        g_xpt[((long)b*Ll + lp)*Dd + d] = v;
    }
}

// ---------------- kernel 2: projections (x_dbl split + dt proj + softplus) ----
__global__ void __launch_bounds__(128) k_proj(const float* __restrict__ xw,
                                              const float* __restrict__ dtw,
                                              const float* __restrict__ dtb){
    __shared__ float swx [2*C38*Dd];
    __shared__ float swdt[2*Dd*Rr];
    __shared__ float sbia[2*Dd];
    int o = blockIdx.y, b = blockIdx.z;
    int tid = threadIdx.x;
    for (int i=tid;i<2*C38*Dd;i+=128){
        int ki = i/(C38*Dd); int rem = i - ki*(C38*Dd);
        swx[i] = xw[(o + 2*ki)*C38*Dd + rem];
    }
    for (int i=tid;i<2*Dd*Rr;i+=128){
        int ki = i/(Dd*Rr); int rem = i - ki*(Dd*Rr);
        swdt[i] = dtw[(o + 2*ki)*Dd*Rr + rem];
    }
    for (int i=tid;i<2*Dd;i+=128){
        int ki = i/Dd; int rem = i - ki*Dd;
        sbia[i] = dtb[(o + 2*ki)*Dd + rem];
    }
    __syncthreads();

    int p = blockIdx.x*128 + tid;
    const float* xp = (o==0 ? g_xpf : g_xpt) + ((long)b*Ll + p)*Dd;
    float xv[Dd];
    #pragma unroll
    for (int i=0;i<Dd/4;i++){
        float4 v = reinterpret_cast<const float4*>(xp)[i];
        xv[4*i]=v.x; xv[4*i+1]=v.y; xv[4*i+2]=v.z; xv[4*i+3]=v.w;
    }

    for (int ki=0; ki<2; ki++){
        int k = o + 2*ki;
        int l = (ki==0) ? p : (Ll-1-p);
        const float* wk = swx + ki*C38*Dd;
        long bkl = ((long)(b*Kk + k))*Ll + l;

        // dts (first R rows)
        float dts[Rr];
        #pragma unroll
        for (int c=0;c<Rr;c++){
            float acc = 0.f;
            #pragma unroll
            for (int d=0; d<Dd; d++) acc += xv[d]*wk[c*Dd+d];
            dts[c] = acc;
        }
        // Bs rows
        for (int cc=0; cc<Nn/4; cc++){
            const float* w0 = wk + (Rr + 4*cc)*Dd;
            float a0=0,a1=0,a2=0,a3=0;
            #pragma unroll
            for (int d=0; d<Dd; d++){
                float xd = xv[d];
                a0 += xd*w0[d]; a1 += xd*w0[Dd+d];
                a2 += xd*w0[2*Dd+d]; a3 += xd*w0[3*Dd+d];
            }
            reinterpret_cast<float4*>(g_Bsc + bkl*Nn)[cc] = make_float4(a0,a1,a2,a3);
        }
        // Cs rows
        for (int cc=0; cc<Nn/4; cc++){
            const float* w0 = wk + (Rr + Nn + 4*cc)*Dd;
            float a0=0,a1=0,a2=0,a3=0;
            #pragma unroll
            for (int d=0; d<Dd; d++){
                float xd = xv[d];
                a0 += xd*w0[d]; a1 += xd*w0[Dd+d];
                a2 += xd*w0[2*Dd+d]; a3 += xd*w0[3*Dd+d];
            }
            reinterpret_cast<float4*>(g_Csc + bkl*Nn)[cc] = make_float4(a0,a1,a2,a3);
        }
        // delta = softplus(dts @ dtW + bias); store (delta, delta*u)
        const float* wd  = swdt + ki*Dd*Rr;
        const float* bia = sbia + ki*Dd;
        float4* dout = reinterpret_cast<float4*>(g_ddu + bkl*Dd);
        for (int dd=0; dd<Dd; dd+=2){
            float aa[2];
            #pragma unroll
            for (int q=0;q<2;q++){
                float acc = bia[dd+q];
                #pragma unroll
                for (int r=0;r<Rr;r++) acc += dts[r]*wd[(dd+q)*Rr + r];
                aa[q] = softplus_f(acc);
            }
            dout[dd>>1] = make_float4(aa[0], aa[0]*xv[dd], aa[1], aa[1]*xv[dd+1]);
        }
    }
}

// ---------------- kernel 3: pass A (chunk-local scan, zero init) --------------
__global__ void __launch_bounds__(Dd) k_scanA(const float* __restrict__ A_logs){
    __shared__ float4 sB[LCk*Nn/4];
    int c = blockIdx.x, k = blockIdx.y, b = blockIdx.z;
    int d = threadIdx.x;
    long bk = (long)b*Kk + k;

    const float4* gB4 = reinterpret_cast<const float4*>(g_Bsc + (bk*Ll + (long)c*LCk)*Nn);
    for (int i=d; i<LCk*Nn/4; i+=Dd) sB[i] = gB4[i];
    __syncthreads();

    float A2[Nn];
    const float* al = A_logs + (k*Dd + d)*Nn;
    #pragma unroll
    for (int n=0;n<Nn;n++) A2[n] = -__expf(al[n]) * 1.4426950408889634f;

    float h[Nn];
    #pragma unroll
    for (int n=0;n<Nn;n++) h[n] = 0.f;
    float S = 0.f;

    const float2* dptr = g_ddu + (bk*Ll + (long)c*LCk)*Dd + d;

    float2 cur[4];
    #pragma unroll
    for (int i=0;i<4;i++) cur[i] = dptr[i*Dd];

    for (int jb=0; jb<LCk; jb+=4){
        float2 nxt[4];
        if (jb+4 < LCk){
            #pragma unroll
            for (int i=0;i<4;i++) nxt[i] = dptr[(jb+4+i)*Dd];
        }
        #pragma unroll
        for (int i=0;i<4;i++){
            float dlt = cur[i].x, du = cur[i].y;
            S += dlt;
            const float4* bj = sB + (jb+i)*(Nn/4);
            #pragma unroll
            for (int q=0;q<Nn/4;q++){
                float4 bb = bj[q];
                h[4*q+0] = h[4*q+0]*ex2f(dlt*A2[4*q+0]) + du*bb.x;
                h[4*q+1] = h[4*q+1]*ex2f(dlt*A2[4*q+1]) + du*bb.y;
                h[4*q+2] = h[4*q+2]*ex2f(dlt*A2[4*q+2]) + du*bb.z;
                h[4*q+3] = h[4*q+3]*ex2f(dlt*A2[4*q+3]) + du*bb.w;
            }
        }
        #pragma unroll
        for (int i=0;i<4;i++) cur[i] = nxt[i];
    }
    long base = ((bk*NCk + c)*Dd + d)*Nn;   // in float2 units
    float4* pp = reinterpret_cast<float4*>(g_Phc + base);
    #pragma unroll
    for (int q=0;q<Nn/2;q++){
        pp[q] = make_float4(ex2f(A2[2*q]*S),   h[2*q],
                            ex2f(A2[2*q+1]*S), h[2*q+1]);
    }
}

// ---------------- kernel 4: inter-chunk scan (software-pipelined loads) ------
#define MID_G 16
#define MID_NG (NCk/MID_G)
__global__ void __launch_bounds__(256) k_mid(){
    int g = blockIdx.x*blockDim.x + threadIdx.x;   // B*K*D*N threads
    if (g >= Bsz*Kk*Dd*Nn) return;
    const int STR = Dd*Nn;                         // stride between chunks
    long base0 = g + ((long)(g / (Dd*Nn))) * (long)(NCk-1) * STR;

    float2 PH[2][MID_G];

    #pragma unroll
    for (int i=0;i<MID_G;i++)
        PH[0][i] = g_Phc[base0 + (long)i*STR];

    float hin = 0.f;
    #pragma unroll
    for (int grp=0; grp<MID_NG; grp++){
        int cur = grp & 1, nxt = cur ^ 1;
        if (grp+1 < MID_NG){
            #pragma unroll
            for (int i=0;i<MID_G;i++)
                PH[nxt][i] = g_Phc[base0 + (long)((grp+1)*MID_G + i)*STR];
        }
        #pragma unroll
        for (int i=0;i<MID_G;i++){
            long idx = base0 + (long)(grp*MID_G + i)*STR;
            g_hin[idx] = hin;
            hin = hin*PH[cur][i].x + PH[cur][i].y;
        }
    }
}

// ---------------- kernel 5: pass B (replay with correct h_in, emit y) --------
__global__ void __launch_bounds__(Dd) k_scanB(const float* __restrict__ A_logs){
    __shared__ float4 sB[LCk*Nn/4];
    __shared__ float4 sC[LCk*Nn/4];
    int c = blockIdx.x, k = blockIdx.y, b = blockIdx.z;
    int d = threadIdx.x;
    long bk = (long)b*Kk + k;

    const float4* gB4 = reinterpret_cast<const float4*>(g_Bsc + (bk*Ll + (long)c*LCk)*Nn);
    const float4* gC4 = reinterpret_cast<const float4*>(g_Csc + (bk*Ll + (long)c*LCk)*Nn);
    for (int i=d; i<LCk*Nn/4; i+=Dd){ sB[i] = gB4[i]; sC[i] = gC4[i]; }
    __syncthreads();

    float A2[Nn];
    const float* al = A_logs + (k*Dd + d)*Nn;
    #pragma unroll
    for (int n=0;n<Nn;n++) A2[n] = -__expf(al[n]) * 1.4426950408889634f;

    float h[Nn];
    long base = ((bk*NCk + c)*Dd + d)*Nn;
    #pragma unroll
    for (int q=0;q<Nn/4;q++){
        float4 v = reinterpret_cast<const float4*>(g_hin + base)[q];
        h[4*q]=v.x; h[4*q+1]=v.y; h[4*q+2]=v.z; h[4*q+3]=v.w;
    }

    const float2* dptr = g_ddu + (bk*Ll + (long)c*LCk)*Dd + d;
    int l0 = c*LCk;
    float* yout = g_ys + ((long)k*Bsz + b)*Ll*Dd + d;

    float2 cur[4];
    #pragma unroll
    for (int i=0;i<4;i++) cur[i] = dptr[i*Dd];

    for (int jb=0; jb<LCk; jb+=4){
        float2 nxt[4];
        if (jb+4 < LCk){
            #pragma unroll
            for (int i=0;i<4;i++) nxt[i] = dptr[(jb+4+i)*Dd];
        }
        #pragma unroll
        for (int i=0;i<4;i++){
            float dlt = cur[i].x, du = cur[i].y;
            float y = 0.f;
            const float4* bj = sB + (jb+i)*(Nn/4);
            const float4* cj = sC + (jb+i)*(Nn/4);
            #pragma unroll
            for (int q=0;q<Nn/4;q++){
                float4 bb = bj[q];
                float4 cc = cj[q];
                h[4*q+0] = h[4*q+0]*ex2f(dlt*A2[4*q+0]) + du*bb.x;  y += h[4*q+0]*cc.x;
                h[4*q+1] = h[4*q+1]*ex2f(dlt*A2[4*q+1]) + du*bb.y;  y += h[4*q+1]*cc.y;
                h[4*q+2] = h[4*q+2]*ex2f(dlt*A2[4*q+2]) + du*bb.z;  y += h[4*q+2]*cc.z;
                h[4*q+3] = h[4*q+3]*ex2f(dlt*A2[4*q+3]) + du*bb.w;  y += h[4*q+3]*cc.w;
            }
            int l = l0 + jb + i;
            int t;
            if (k == 0)      t = l;
            else if (k == 1) t = ((l & 63) << 6) | (l >> 6);
            else if (k == 2) t = Ll-1-l;
            else { int q2 = Ll-1-l; t = ((q2 & 63) << 6) | (q2 >> 6); }
            yout[(long)t*Dd] = y;
        }
        #pragma unroll
        for (int i=0;i<4;i++) cur[i] = nxt[i];
    }
}

// ---------------- kernel 6: 4-way merge + D-skip + LayerNorm ------------------
__global__ void __launch_bounds__(256) k_merge(const float* __restrict__ Ds,
                                               const float* __restrict__ lnw,
                                               const float* __restrict__ lnb,
                                               float* __restrict__ out){
    const long BLD = (long)Bsz*Ll*Dd;
    int warp = threadIdx.x >> 5, lane = threadIdx.x & 31;
    int pos = blockIdx.x*8 + warp;
    int b = pos >> 12;              // Ll = 4096
    int l = pos & (Ll-1);
    long base = ((long)b*Ll + l)*Dd;
    float s[3]; float sum = 0.f, sq = 0.f;
    #pragma unroll
    for (int i=0;i<3;i++){
        int dch = lane + 32*i;
        long off = base + dch;
        float dsum = Ds[dch] + Ds[Dd+dch] + Ds[2*Dd+dch] + Ds[3*Dd+dch];
        float v = g_ys[off] + g_ys[off + BLD] + g_ys[off + 2*BLD] + g_ys[off + 3*BLD]
                + dsum * g_xpf[off];
        s[i] = v; sum += v; sq += v*v;
    }
    #pragma unroll
    for (int o2=16;o2>0;o2>>=1){
        sum += __shfl_xor_sync(0xffffffffu, sum, o2);
        sq  += __shfl_xor_sync(0xffffffffu, sq,  o2);
    }
    float mean = sum * (1.f/Dd);
    float var  = sq  * (1.f/Dd) - mean*mean;
    float inv  = rsqrtf(var + 1e-5f);
    #pragma unroll
    for (int i=0;i<3;i++){
        int dch = lane + 32*i;
        out[base + dch] = (s[i]-mean)*inv*lnw[dch] + lnb[dch];
    }
}

// ---------------- launch ------------------------------------------------------
extern "C" void kernel_launch(void* const* d_in, const int* in_sizes, int n_in,
                              void* d_out, int out_size){
    const float* x     = (const float*)d_in[0];
    const float* xw    = (const float*)d_in[1];
    const float* dtw   = (const float*)d_in[2];
    const float* dtb   = (const float*)d_in[3];
    const float* alogs = (const float*)d_in[4];
    const float* Ds    = (const float*)d_in[5];
    const float* lnw   = (const float*)d_in[6];
    const float* lnb   = (const float*)d_in[7];
    float* out = (float*)d_out;

    k_transpose<<<dim3(Ll/32, Dd/32, Bsz), dim3(32,8)>>>(x);
    k_proj     <<<dim3(Ll/128, 2, Bsz), 128>>>(xw, dtw, dtb);
    k_scanA    <<<dim3(NCk, Kk, Bsz), Dd>>>(alogs);
    k_mid      <<<(Bsz*Kk*Dd*Nn + 255)/256, 256>>>();
    k_scanB    <<<dim3(NCk, Kk, Bsz), Dd>>>(alogs);
    k_merge    <<<Bsz*Ll/8, 256>>>(Ds, lnw, lnb, out);
}

// round 13
// speedup vs baseline: 1.1845x; 1.0466x over previous
#include <cuda_runtime.h>
#include <math.h>

#define Bsz 4
#define Dd  96
#define Hh  64
#define Ww  64
#define Ll  4096
#define Kk  4
#define Nn  16
#define Rr  6
#define C38 38
#define NCk 64   // number of chunks
#define LCk 64   // chunk length (NCk*LCk == Ll)

// ---------------- scratch (__device__ globals; no allocations) ----------------
__device__ float  g_xpf  [Bsz*Ll*Dd];           // x permuted (B,L,D), row-major spatial
__device__ float  g_xpt  [Bsz*Ll*Dd];           // x permuted (B,L,D), col-major spatial
__device__ float2 g_ddu  [Bsz*Kk*Ll*Dd];        // (softplus delta, delta*u) (B,K,L,D)
__device__ float  g_Bsc  [Bsz*Kk*Ll*Nn];        // Bs (B,K,L,N)
__device__ float  g_Csc  [Bsz*Kk*Ll*Nn];        // Cs (B,K,L,N)
__device__ float2 g_Phc  [Bsz*Kk*NCk*Dd*Nn];    // interleaved (chunk decay P, end state hc)
__device__ float  g_hin  [Bsz*Kk*NCk*Dd*Nn];    // chunk incoming states
__device__ float  g_ys   [Kk*Bsz*Ll*Dd];        // per-direction y in merge-target space

__device__ __forceinline__ float ex2f(float x){
    float r; asm("ex2.approx.ftz.f32 %0, %1;" : "=f"(r) : "f"(x)); return r;
}
__device__ __forceinline__ float lg2f(float x){
    float r; asm("lg2.approx.ftz.f32 %0, %1;" : "=f"(r) : "f"(x)); return r;
}
__device__ __forceinline__ float softplus_f(float x){
    float e = ex2f(-fabsf(x)*1.4426950408889634f);
    return fmaxf(x, 0.f) + 0.6931471805599453f*lg2f(1.f + e);
}
// packed f32x2 (Blackwell): FFMA2/FMUL2 only reachable via PTX
__device__ __forceinline__ float2 mul2(float2 a, float2 b){
    unsigned long long ra = *reinterpret_cast<unsigned long long*>(&a);
    unsigned long long rb = *reinterpret_cast<unsigned long long*>(&b);
    unsigned long long rc;
    asm("mul.rn.f32x2 %0, %1, %2;" : "=l"(rc) : "l"(ra), "l"(rb));
    return *reinterpret_cast<float2*>(&rc);
}
__device__ __forceinline__ float2 fma2(float2 a, float2 b, float2 c){
    unsigned long long ra = *reinterpret_cast<unsigned long long*>(&a);
    unsigned long long rb = *reinterpret_cast<unsigned long long*>(&b);
    unsigned long long rc = *reinterpret_cast<unsigned long long*>(&c);
    unsigned long long rd;
    asm("fma.rn.f32x2 %0, %1, %2, %3;" : "=l"(rd) : "l"(ra), "l"(rb), "l"(rc));
    return *reinterpret_cast<float2*>(&rd);
}

// ---------------- kernel 1: transpose x -> (B,L,D) in both traversal orders ---
__global__ void k_transpose(const float* __restrict__ x){
    __shared__ float tile[32][33];
    int b = blockIdx.z, d0 = blockIdx.y*32, l0 = blockIdx.x*32;
    int tx = threadIdx.x, ty = threadIdx.y;     // block (32,8)
    #pragma unroll
    for (int i=0;i<4;i++){
        tile[ty+8*i][tx] = x[((long)b*Dd + d0+ty+8*i)*Ll + l0+tx];
    }
    __syncthreads();
    #pragma unroll
    for (int i=0;i<4;i++){
        int l = l0 + ty + 8*i;
        int d = d0 + tx;
        float v = tile[tx][ty+8*i];
        g_xpf[((long)b*Ll + l)*Dd + d] = v;
        int lp = ((l & 63) << 6) | (l >> 6);    // spatial transpose index
        g_xpt[((long)b*Ll + lp)*Dd + d] = v;
    }
}

// ---------------- kernel 2: projections, f32x2 fused GEMV ---------------------
// smem weight layout: [ki][d][40 slots]: dts c=0..5 -> slot c; B c=6..21 -> slot c+2;
// C c=22..37 -> slot c+2. Slots 6,7 zero pad. Row stride 40 floats (160B).
__global__ void __launch_bounds__(128) k_proj(const float* __restrict__ xw,
                                              const float* __restrict__ dtw,
                                              const float* __restrict__ dtb){
    __shared__ float swx [2*Dd*40];
    __shared__ float swdt[2*Dd*Rr];
    __shared__ float sbia[2*Dd];
    int o = blockIdx.y, b = blockIdx.z;
    int tid = threadIdx.x;
    for (int i=tid;i<2*Dd*40;i+=128) swx[i] = 0.f;
    __syncthreads();
    for (int i=tid;i<2*C38*Dd;i+=128){
        int ki = i/(C38*Dd); int rem = i - ki*(C38*Dd);
        int c = rem/Dd, d = rem - c*Dd;
        int slot = (c < Rr) ? c : c+2;
        swx[ki*Dd*40 + d*40 + slot] = xw[(o + 2*ki)*C38*Dd + rem];
    }
    for (int i=tid;i<2*Dd*Rr;i+=128){
        int ki = i/(Dd*Rr); int rem = i - ki*(Dd*Rr);
        swdt[i] = dtw[(o + 2*ki)*Dd*Rr + rem];
    }
    for (int i=tid;i<2*Dd;i+=128){
        int ki = i/Dd; int rem = i - ki*Dd;
        sbia[i] = dtb[(o + 2*ki)*Dd + rem];
    }
    __syncthreads();

    int p = blockIdx.x*128 + tid;
    const float* xp = (o==0 ? g_xpf : g_xpt) + ((long)b*Ll + p)*Dd;
    float xv[Dd];
    #pragma unroll
    for (int i=0;i<Dd/4;i++){
        float4 v = reinterpret_cast<const float4*>(xp)[i];
        xv[4*i]=v.x; xv[4*i+1]=v.y; xv[4*i+2]=v.z; xv[4*i+3]=v.w;
    }

    for (int ki=0; ki<2; ki++){
        int k = o + 2*ki;
        int l = (ki==0) ? p : (Ll-1-p);
        long bkl = ((long)(b*Kk + k))*Ll + l;

        float2 acc[20];
        #pragma unroll
        for (int t=0;t<20;t++) acc[t] = make_float2(0.f,0.f);

        const float* wbase = swx + ki*Dd*40;
        #pragma unroll 4
        for (int d=0; d<Dd; d++){
            float2 xd2 = make_float2(xv[d], xv[d]);
            const float4* wrow = reinterpret_cast<const float4*>(wbase + d*40);
            #pragma unroll
            for (int t=0;t<10;t++){
                float4 w4 = wrow[t];
                acc[2*t]   = fma2(make_float2(w4.x,w4.y), xd2, acc[2*t]);
                acc[2*t+1] = fma2(make_float2(w4.z,w4.w), xd2, acc[2*t+1]);
            }
        }

        // Bs: slots 8..23 = pairs 4..11
        float4* Bo = reinterpret_cast<float4*>(g_Bsc + bkl*Nn);
        Bo[0] = make_float4(acc[4].x,acc[4].y,acc[5].x,acc[5].y);
        Bo[1] = make_float4(acc[6].x,acc[6].y,acc[7].x,acc[7].y);
        Bo[2] = make_float4(acc[8].x,acc[8].y,acc[9].x,acc[9].y);
        Bo[3] = make_float4(acc[10].x,acc[10].y,acc[11].x,acc[11].y);
        // Cs: slots 24..39 = pairs 12..19
        float4* Co = reinterpret_cast<float4*>(g_Csc + bkl*Nn);
        Co[0] = make_float4(acc[12].x,acc[12].y,acc[13].x,acc[13].y);
        Co[1] = make_float4(acc[14].x,acc[14].y,acc[15].x,acc[15].y);
        Co[2] = make_float4(acc[16].x,acc[16].y,acc[17].x,acc[17].y);
        Co[3] = make_float4(acc[18].x,acc[18].y,acc[19].x,acc[19].y);

        float dts[Rr] = {acc[0].x, acc[0].y, acc[1].x, acc[1].y, acc[2].x, acc[2].y};

        // delta = softplus(dts @ dtW + bias); store (delta, delta*u)
        const float* wd  = swdt + ki*Dd*Rr;
        const float* bia = sbia + ki*Dd;
        float4* dout = reinterpret_cast<float4*>(g_ddu + bkl*Dd);
        for (int dd=0; dd<Dd; dd+=2){
            float aa[2];
            #pragma unroll
            for (int q=0;q<2;q++){
                float a2 = bia[dd+q];
                #pragma unroll
                for (int r=0;r<Rr;r++) a2 += dts[r]*wd[(dd+q)*Rr + r];
                aa[q] = softplus_f(a2);
            }
            dout[dd>>1] = make_float4(aa[0], aa[0]*xv[dd], aa[1], aa[1]*xv[dd+1]);
        }
    }
}

// ---------------- kernel 3: pass A (chunk-local scan, f32x2) ------------------
__global__ void __launch_bounds__(Dd) k_scanA(const float* __restrict__ A_logs){
    __shared__ float4 sB[LCk*Nn/4];
    int c = blockIdx.x, k = blockIdx.y, b = blockIdx.z;
    int d = threadIdx.x;
    long bk = (long)b*Kk + k;

    const float4* gB4 = reinterpret_cast<const float4*>(g_Bsc + (bk*Ll + (long)c*LCk)*Nn);
    for (int i=d; i<LCk*Nn/4; i+=Dd) sB[i] = gB4[i];
    __syncthreads();

    float2 A2[8];
    const float* al = A_logs + (k*Dd + d)*Nn;
    #pragma unroll
    for (int q=0;q<8;q++)
        A2[q] = make_float2(-__expf(al[2*q])*1.4426950408889634f,
                            -__expf(al[2*q+1])*1.4426950408889634f);

    float2 h[8];
    #pragma unroll
    for (int q=0;q<8;q++) h[q] = make_float2(0.f,0.f);
    float S = 0.f;

    const float2* dptr = g_ddu + (bk*Ll + (long)c*LCk)*Dd + d;

    float2 cur[4];
    #pragma unroll
    for (int i=0;i<4;i++) cur[i] = dptr[i*Dd];

    for (int jb=0; jb<LCk; jb+=4){
        float2 nxt[4];
        if (jb+4 < LCk){
            #pragma unroll
            for (int i=0;i<4;i++) nxt[i] = dptr[(jb+4+i)*Dd];
        }
        #pragma unroll
        for (int i=0;i<4;i++){
            float dlt = cur[i].x, du = cur[i].y;
            S += dlt;
            float2 dlt2 = make_float2(dlt,dlt);
            float2 du2  = make_float2(du,du);
            const float4* bj = sB + (jb+i)*(Nn/4);
            #pragma unroll
            for (int q=0;q<Nn/4;q++){
                float4 bb = bj[q];
                float2 a0 = mul2(A2[2*q],   dlt2);
                float2 a1 = mul2(A2[2*q+1], dlt2);
                float2 e0 = make_float2(ex2f(a0.x), ex2f(a0.y));
                float2 e1 = make_float2(ex2f(a1.x), ex2f(a1.y));
                float2 db0 = mul2(make_float2(bb.x,bb.y), du2);
                float2 db1 = mul2(make_float2(bb.z,bb.w), du2);
                h[2*q]   = fma2(h[2*q],   e0, db0);
                h[2*q+1] = fma2(h[2*q+1], e1, db1);
            }
        }
        #pragma unroll
        for (int i=0;i<4;i++) cur[i] = nxt[i];
    }
    long base = ((bk*NCk + c)*Dd + d)*Nn;   // in float2 units
    float4* pp = reinterpret_cast<float4*>(g_Phc + base);
    #pragma unroll
    for (int q=0;q<8;q++){
        pp[q] = make_float4(ex2f(A2[q].x*S), h[q].x,
                            ex2f(A2[q].y*S), h[q].y);
    }
}

// ---------------- kernel 4: inter-chunk scan (software-pipelined loads) ------
#define MID_G 16
#define MID_NG (NCk/MID_G)
__global__ void __launch_bounds__(256) k_mid(){
    int g = blockIdx.x*blockDim.x + threadIdx.x;   // B*K*D*N threads
    if (g >= Bsz*Kk*Dd*Nn) return;
    const int STR = Dd*Nn;                         // stride between chunks
    long base0 = g + ((long)(g / (Dd*Nn))) * (long)(NCk-1) * STR;

    float2 PH[2][MID_G];

    #pragma unroll
    for (int i=0;i<MID_G;i++)
        PH[0][i] = g_Phc[base0 + (long)i*STR];

    float hin = 0.f;
    #pragma unroll
    for (int grp=0; grp<MID_NG; grp++){
        int cur = grp & 1, nxt = cur ^ 1;
        if (grp+1 < MID_NG){
            #pragma unroll
            for (int i=0;i<MID_G;i++)
                PH[nxt][i] = g_Phc[base0 + (long)((grp+1)*MID_G + i)*STR];
        }
        #pragma unroll
        for (int i=0;i<MID_G;i++){
            long idx = base0 + (long)(grp*MID_G + i)*STR;
            g_hin[idx] = hin;
            hin = hin*PH[cur][i].x + PH[cur][i].y;
        }
    }
}

// ---------------- kernel 5: pass B (replay with h_in, f32x2, emit y) ---------
__global__ void __launch_bounds__(Dd) k_scanB(const float* __restrict__ A_logs){
    __shared__ float4 sB[LCk*Nn/4];
    __shared__ float4 sC[LCk*Nn/4];
    int c = blockIdx.x, k = blockIdx.y, b = blockIdx.z;
    int d = threadIdx.x;
    long bk = (long)b*Kk + k;

    const float4* gB4 = reinterpret_cast<const float4*>(g_Bsc + (bk*Ll + (long)c*LCk)*Nn);
    const float4* gC4 = reinterpret_cast<const float4*>(g_Csc + (bk*Ll + (long)c*LCk)*Nn);
    for (int i=d; i<LCk*Nn/4; i+=Dd){ sB[i] = gB4[i]; sC[i] = gC4[i]; }
    __syncthreads();

    float2 A2[8];
    const float* al = A_logs + (k*Dd + d)*Nn;
    #pragma unroll
    for (int q=0;q<8;q++)
        A2[q] = make_float2(-__expf(al[2*q])*1.4426950408889634f,
                            -__expf(al[2*q+1])*1.4426950408889634f);

    float2 h[8];
    long base = ((bk*NCk + c)*Dd + d)*Nn;
    #pragma unroll
    for (int q=0;q<8;q++){
        h[q] = reinterpret_cast<const float2*>(g_hin + base)[q];
    }

    const float2* dptr = g_ddu + (bk*Ll + (long)c*LCk)*Dd + d;
    int l0 = c*LCk;
    float* yout = g_ys + ((long)k*Bsz + b)*Ll*Dd + d;

    float2 cur[4];
    #pragma unroll
    for (int i=0;i<4;i++) cur[i] = dptr[i*Dd];

    for (int jb=0; jb<LCk; jb+=4){
        float2 nxt[4];
        if (jb+4 < LCk){
            #pragma unroll
            for (int i=0;i<4;i++) nxt[i] = dptr[(jb+4+i)*Dd];
        }
        #pragma unroll
        for (int i=0;i<4;i++){
            float dlt = cur[i].x, du = cur[i].y;
            float2 dlt2 = make_float2(dlt,dlt);
            float2 du2  = make_float2(du,du);
            float2 y2   = make_float2(0.f,0.f);
            const float4* bj = sB + (jb+i)*(Nn/4);
            const float4* cj = sC + (jb+i)*(Nn/4);
            #pragma unroll
            for (int q=0;q<Nn/4;q++){
                float4 bb = bj[q];
                float4 cc = cj[q];
                float2 a0 = mul2(A2[2*q],   dlt2);
                float2 a1 = mul2(A2[2*q+1], dlt2);
                float2 e0 = make_float2(ex2f(a0.x), ex2f(a0.y));
                float2 e1 = make_float2(ex2f(a1.x), ex2f(a1.y));
                float2 db0 = mul2(make_float2(bb.x,bb.y), du2);
                float2 db1 = mul2(make_float2(bb.z,bb.w), du2);
                h[2*q]   = fma2(h[2*q],   e0, db0);
                h[2*q+1] = fma2(h[2*q+1], e1, db1);
                y2 = fma2(h[2*q],   make_float2(cc.x,cc.y), y2);
                y2 = fma2(h[2*q+1], make_float2(cc.z,cc.w), y2);
            }
            float y = y2.x + y2.y;
            int l = l0 + jb + i;
            int t;
            if (k == 0)      t = l;
            else if (k == 1) t = ((l & 63) << 6) | (l >> 6);
            else if (k == 2) t = Ll-1-l;
            else { int q2 = Ll-1-l; t = ((q2 & 63) << 6) | (q2 >> 6); }
            yout[(long)t*Dd] = y;
        }
        #pragma unroll
        for (int i=0;i<4;i++) cur[i] = nxt[i];
    }
}

// ---------------- kernel 6: 4-way merge + D-skip + LayerNorm ------------------
__global__ void __launch_bounds__(256) k_merge(const float* __restrict__ Ds,
                                               const float* __restrict__ lnw,
                                               const float* __restrict__ lnb,
                                               float* __restrict__ out){
    const long BLD = (long)Bsz*Ll*Dd;
    int warp = threadIdx.x >> 5, lane = threadIdx.x & 31;
    int pos = blockIdx.x*8 + warp;
    int b = pos >> 12;              // Ll = 4096
    int l = pos & (Ll-1);
    long base = ((long)b*Ll + l)*Dd;
    float s[3]; float sum = 0.f, sq = 0.f;
    #pragma unroll
    for (int i=0;i<3;i++){
        int dch = lane + 32*i;
        long off = base + dch;
        float dsum = Ds[dch] + Ds[Dd+dch] + Ds[2*Dd+dch] + Ds[3*Dd+dch];
        float v = g_ys[off] + g_ys[off + BLD] + g_ys[off + 2*BLD] + g_ys[off + 3*BLD]
                + dsum * g_xpf[off];
        s[i] = v; sum += v; sq += v*v;
    }
    #pragma unroll
    for (int o2=16;o2>0;o2>>=1){
        sum += __shfl_xor_sync(0xffffffffu, sum, o2);
        sq  += __shfl_xor_sync(0xffffffffu, sq,  o2);
    }
    float mean = sum * (1.f/Dd);
    float var  = sq  * (1.f/Dd) - mean*mean;
    float inv  = rsqrtf(var + 1e-5f);
    #pragma unroll
    for (int i=0;i<3;i++){
        int dch = lane + 32*i;
        out[base + dch] = (s[i]-mean)*inv*lnw[dch] + lnb[dch];
    }
}

// ---------------- launch ------------------------------------------------------
extern "C" void kernel_launch(void* const* d_in, const int* in_sizes, int n_in,
                              void* d_out, int out_size){
    const float* x     = (const float*)d_in[0];
    const float* xw    = (const float*)d_in[1];
    const float* dtw   = (const float*)d_in[2];
    const float* dtb   = (const float*)d_in[3];
    const float* alogs = (const float*)d_in[4];
    const float* Ds    = (const float*)d_in[5];
    const float* lnw   = (const float*)d_in[6];
    const float* lnb   = (const float*)d_in[7];
    float* out = (float*)d_out;

    k_transpose<<<dim3(Ll/32, Dd/32, Bsz), dim3(32,8)>>>(x);
    k_proj     <<<dim3(Ll/128, 2, Bsz), 128>>>(xw, dtw, dtb);
    k_scanA    <<<dim3(NCk, Kk, Bsz), Dd>>>(alogs);
    k_mid      <<<(Bsz*Kk*Dd*Nn + 255)/256, 256>>>();
    k_scanB    <<<dim3(NCk, Kk, Bsz), Dd>>>(alogs);
    k_merge    <<<Bsz*Ll/8, 256>>>(Ds, lnw, lnb, out);
}